// round 16
// baseline (speedup 1.0000x reference)
#include <cuda_runtime.h>
#include <cuda_bf16.h>
#include <cstdint>

#define B_ 4
#define S_ 2048
#define D_ 1024
#define H_ 16
#define E_ 64
#define M_ (B_*S_)   // 8192

// Scratch (allocation-free rule: __device__ globals)
__device__ float g_Q [(size_t)B_*H_*S_*E_];  // (B,H,S,E) pre-scaled 0.125*log2e, tf32-rounded
__device__ float g_K [(size_t)B_*H_*S_*E_];  // (B,H,S,E) tf32-rounded
__device__ float g_Vt[(size_t)B_*H_*E_*S_];  // (B,H,E,S) V transposed, tf32-rounded
__device__ float g_Z [(size_t)B_*S_*H_*E_];  // (B,S,H*E) tf32-rounded (att epilogue)
__device__ float g_Xr[(size_t)M_*D_];        // tf32-rounded x
// Pre-transposed (and tf32-rounded) weights: [h][e][k] / [n][k]
__device__ float g_WTq[(size_t)H_*E_*D_];
__device__ float g_WTk[(size_t)H_*E_*D_];
__device__ float g_WTv[(size_t)H_*E_*D_];
__device__ float g_WTo[(size_t)D_*D_];

#define QSCL 0.1803368801111204f   // 0.125 * log2(e)

// ---------------------------------------------------------------------------
// Helpers
// ---------------------------------------------------------------------------
__device__ __forceinline__ float tf32r(float x) {
    asm("cvt.rna.tf32.f32 %0, %1;" : "=f"(x) : "f"(x));
    return x;
}
__device__ __forceinline__ unsigned fu(float x) { return __float_as_uint(x); }

__device__ __forceinline__ void mma8(float* d, const unsigned* a,
                                     unsigned b0, unsigned b1) {
    asm volatile(
        "mma.sync.aligned.m16n8k8.row.col.f32.tf32.tf32.f32 "
        "{%0,%1,%2,%3}, {%4,%5,%6,%7}, {%8,%9}, {%0,%1,%2,%3};\n"
        : "+f"(d[0]), "+f"(d[1]), "+f"(d[2]), "+f"(d[3])
        : "r"(a[0]), "r"(a[1]), "r"(a[2]), "r"(a[3]), "r"(b0), "r"(b1));
}

__device__ __forceinline__ uint32_t smem_u32(const void* p) {
    uint32_t a;
    asm("{ .reg .u64 t; cvta.to.shared.u64 t, %1; cvt.u32.u64 %0, t; }"
        : "=r"(a) : "l"(p));
    return a;
}

#define LDSM4(r0, r1, r2, r3, addr) \
    asm volatile("ldmatrix.sync.aligned.m8n8.x4.shared.b16 {%0,%1,%2,%3}, [%4];" \
        : "=r"(r0), "=r"(r1), "=r"(r2), "=r"(r3) : "r"(addr))

#define CP16(dst, src) \
    asm volatile("cp.async.cg.shared.global [%0], [%1], 16;" \
        :: "r"(dst), "l"(src) : "memory")
#define CP_COMMIT() asm volatile("cp.async.commit_group;" ::: "memory")
#define CP_WAIT0()  asm volatile("cp.async.wait_group 0;" ::: "memory")

// SW128 swizzle on byte offsets (rows of 128B)
#define SWZ(x) ((x) ^ (((x) >> 3) & 0x70))

// ---------------------------------------------------------------------------
// Elementwise tf32 rounding of x (once per launch)
// ---------------------------------------------------------------------------
__global__ void round_x(const float* __restrict__ in)
{
    int i = blockIdx.x * blockDim.x + threadIdx.x;
    float4 v = ((const float4*)in)[i];
    v.x = tf32r(v.x); v.y = tf32r(v.y); v.z = tf32r(v.z); v.w = tf32r(v.w);
    ((float4*)g_Xr)[i] = v;
}

// ---------------------------------------------------------------------------
// QKV weight transpose (all three in one launch) + tf32 rounding.
// z = mat*16 + head: out[mat][h][e][k] = round(in[mat][h][k][e])
// ---------------------------------------------------------------------------
__global__ void transpose_qkv(const float* __restrict__ WQ,
                              const float* __restrict__ WK,
                              const float* __restrict__ WV)
{
    __shared__ float t[32][33];
    const int mat = blockIdx.z >> 4;
    const int hh  = blockIdx.z & 15;
    const float* in = ((mat==0) ? WQ : (mat==1) ? WK : WV) + (size_t)hh*D_*E_;
    float* out = ((mat==0) ? g_WTq : (mat==1) ? g_WTk : g_WTv) + (size_t)hh*E_*D_;
    int r0 = blockIdx.x*32, c0 = blockIdx.y*32;
    int tx = threadIdx.x, ty = threadIdx.y;
#pragma unroll
    for (int j = 0; j < 4; ++j)
        t[ty + 8*j][tx] = in[(size_t)(r0 + ty + 8*j)*E_ + c0 + tx];
    __syncthreads();
#pragma unroll
    for (int j = 0; j < 4; ++j)
        out[(size_t)(c0 + ty + 8*j)*D_ + r0 + tx] = tf32r(t[tx][ty + 8*j]);
}

__global__ void transpose_wo(const float* __restrict__ in)
{
    __shared__ float t[32][33];
    int r0 = blockIdx.x*32, c0 = blockIdx.y*32;
    int tx = threadIdx.x, ty = threadIdx.y;
#pragma unroll
    for (int j = 0; j < 4; ++j)
        t[ty + 8*j][tx] = in[(size_t)(r0 + ty + 8*j)*D_ + c0 + tx];
    __syncthreads();
#pragma unroll
    for (int j = 0; j < 4; ++j)
        g_WTo[(size_t)(c0 + ty + 8*j)*D_ + r0 + tx] = tf32r(t[tx][ty + 8*j]);
}

// ---------------------------------------------------------------------------
// GEMM v2: BM=256 x BN=128 x BK=32, 512 threads, 16 warps (4m x 4n),
// warp tile 64x32. cp.async double-buffered, ldmatrix fragments.
// Dynamic smem: 2 stages x (A 32KB + B 16KB) = 96KB.
// A_PTR_EXPR: addr for A row `row` (0..255), k0, chunk f_c.
// B_PTR_EXPR: addr for B row `row` (0..127), k0, chunk f_c.
// ---------------------------------------------------------------------------
#define GEMM_SMEM_BYTES 98304

#define GEMM_BODY(A_PTR_EXPR, B_PTR_EXPR)                                     \
    extern __shared__ char gsm[];                                             \
    const int tid  = threadIdx.x;                                             \
    const int warp = tid >> 5;                                                \
    const int lane = tid & 31;                                                \
    const int t    = lane & 3;  (void)t;                                      \
    const int g    = lane >> 2; (void)g;                                      \
    const int wm   = (warp >> 2) * 64;                                        \
    const int wn   = (warp & 3) * 32;                                         \
    const int f_row = tid >> 3;                                               \
    const int f_c   = tid & 7;                                                \
    const uint32_t sw = (uint32_t)(lane & 7);                                 \
    const uint32_t aSel = (uint32_t)((lane >> 4) & 1);                        \
    const uint32_t bSel = (uint32_t)((lane >> 3) & 1);                        \
    const uint32_t smb = smem_u32(gsm);                                       \
    uint32_t aBase[4], bBase[2];                                              \
    _Pragma("unroll")                                                         \
    for (int mf = 0; mf < 4; ++mf)                                            \
        aBase[mf] = smb + (uint32_t)(wm + mf*16 + (lane & 15)) * 128u;        \
    _Pragma("unroll")                                                         \
    for (int q = 0; q < 2; ++q)                                               \
        bBase[q] = smb + 32768u + (uint32_t)(wn + q*16 + ((lane>>4)&1)*8      \
                                             + (lane & 7)) * 128u;            \
    float acc[4][4][4];                                                       \
    _Pragma("unroll")                                                         \
    for (int i = 0; i < 4; ++i)                                               \
        _Pragma("unroll")                                                     \
        for (int j = 0; j < 4; ++j)                                           \
            _Pragma("unroll")                                                 \
            for (int c = 0; c < 4; ++c) acc[i][j][c] = 0.f;                   \
    {   const int k0 = 0; const uint32_t bo = 0;                              \
        _Pragma("unroll")                                                     \
        for (int p = 0; p < 4; ++p) {                                         \
            int row = f_row + 64*p;                                           \
            CP16(smb + bo + SWZ((uint32_t)(row*128 + f_c*16)), (A_PTR_EXPR)); \
        }                                                                     \
        _Pragma("unroll")                                                     \
        for (int p = 0; p < 2; ++p) {                                         \
            int row = f_row + 64*p;                                           \
            CP16(smb + bo + 32768u + SWZ((uint32_t)(row*128 + f_c*16)),       \
                 (B_PTR_EXPR));                                               \
        }                                                                     \
        CP_COMMIT();                                                          \
    }                                                                         \
    int bb = 0;                                                               \
    for (int kc = 0; kc < 32; ++kc) {                                         \
        CP_WAIT0();                                                           \
        __syncthreads();                                                      \
        if (kc < 31) {                                                        \
            const int k0 = (kc + 1) * 32;                                     \
            const uint32_t bo = (uint32_t)((bb ^ 1) * 49152);                 \
            _Pragma("unroll")                                                 \
            for (int p = 0; p < 4; ++p) {                                     \
                int row = f_row + 64*p;                                       \
                CP16(smb + bo + SWZ((uint32_t)(row*128 + f_c*16)),            \
                     (A_PTR_EXPR));                                           \
            }                                                                 \
            _Pragma("unroll")                                                 \
            for (int p = 0; p < 2; ++p) {                                     \
                int row = f_row + 64*p;                                       \
                CP16(smb + bo + 32768u + SWZ((uint32_t)(row*128 + f_c*16)),   \
                     (B_PTR_EXPR));                                           \
            }                                                                 \
            CP_COMMIT();                                                      \
        }                                                                     \
        const uint32_t bo = (uint32_t)(bb * 49152);                           \
        _Pragma("unroll")                                                     \
        for (int k8 = 0; k8 < 4; ++k8) {                                      \
            const uint32_t ofsA = bo + ((((uint32_t)(2*k8) + aSel) ^ sw) << 4);\
            const uint32_t ofsB = bo + ((((uint32_t)(2*k8) + bSel) ^ sw) << 4);\
            unsigned a[4][4];                                                 \
            _Pragma("unroll")                                                 \
            for (int mf = 0; mf < 4; ++mf)                                    \
                LDSM4(a[mf][0], a[mf][1], a[mf][2], a[mf][3],                 \
                      aBase[mf] + ofsA);                                      \
            _Pragma("unroll")                                                 \
            for (int q = 0; q < 2; ++q) {                                     \
                unsigned b0, b1, b2, b3;                                      \
                LDSM4(b0, b1, b2, b3, bBase[q] + ofsB);                       \
                _Pragma("unroll")                                             \
                for (int mf = 0; mf < 4; ++mf) {                              \
                    mma8(acc[mf][2*q],   a[mf], b0, b1);                      \
                    mma8(acc[mf][2*q+1], a[mf], b2, b3);                      \
                }                                                             \
            }                                                                 \
        }                                                                     \
        bb ^= 1;                                                              \
    }

// ---------------------------------------------------------------------------
// Fused QKV projection. grid (32, 24): y -> mat (y>>3), head-pair (y&7).
// BM=256 rows, BN=128 = exactly one head pair.
// ---------------------------------------------------------------------------
__global__ __launch_bounds__(512, 1) void qkv_kernel(
    const float* __restrict__ bQ, const float* __restrict__ bK,
    const float* __restrict__ bV)
{
    const int m0  = blockIdx.x * 256;
    const int mat = blockIdx.y >> 3;
    const int h0  = (blockIdx.y & 7) * 2;
    const float* WT = ((mat==0) ? g_WTq : (mat==1) ? g_WTk : g_WTv)
                      + (size_t)h0 * E_ * D_;
    const float* bias = ((mat==0) ? bQ : (mat==1) ? bK : bV) + h0*E_;

    GEMM_BODY(
        (g_Xr + (size_t)(m0 + row)*D_ + k0 + f_c*4),
        (WT   + (size_t)row*D_        + k0 + f_c*4))

    if (mat == 2) {
        // V: transposed scatter to g_Vt (B,H,E,S), tf32-rounded
#pragma unroll
        for (int nf = 0; nf < 4; ++nf) {
            int n = wn + nf*8 + 2*t;
            int h = n >> 6, e = n & 63;
            float bi0 = bias[h*E_ + e], bi1 = bias[h*E_ + e + 1];
#pragma unroll
            for (int mf = 0; mf < 4; ++mf) {
                int m = m0 + wm + mf*16 + g;
                int bidx = m >> 11, s = m & (S_-1);
                float* base = g_Vt + (((size_t)(bidx*H_ + h0 + h)*E_ + e)*S_) + s;
                base[0]      = tf32r(acc[mf][nf][0] + bi0);
                base[8]      = tf32r(acc[mf][nf][2] + bi0);
                base[S_]     = tf32r(acc[mf][nf][1] + bi1);
                base[S_ + 8] = tf32r(acc[mf][nf][3] + bi1);
            }
        }
    } else {
        float* out = (mat == 0) ? g_Q : g_K;
        const float scl = (mat == 0) ? QSCL : 1.0f;
#pragma unroll
        for (int nf = 0; nf < 4; ++nf) {
            int n = wn + nf*8 + 2*t;
            int h = n >> 6, e = n & 63;
            float bi0 = bias[h*E_ + e], bi1 = bias[h*E_ + e + 1];
#pragma unroll
            for (int mf = 0; mf < 4; ++mf) {
                int m = m0 + wm + mf*16 + g;
                int bidx = m >> 11, s = m & (S_-1);
                float* r0 = out + ((size_t)(bidx*H_ + h0 + h)*S_ + s)*E_ + e;
                *(float2*)r0 = make_float2(tf32r((acc[mf][nf][0] + bi0)*scl),
                                           tf32r((acc[mf][nf][1] + bi1)*scl));
                *(float2*)(r0 + 8*E_) = make_float2(tf32r((acc[mf][nf][2] + bi0)*scl),
                                                    tf32r((acc[mf][nf][3] + bi1)*scl));
            }
        }
    }
}

// ---------------------------------------------------------------------------
// Output projection. grid (32, 8). g_Z pre-rounded by att epilogue.
// ---------------------------------------------------------------------------
__global__ __launch_bounds__(512, 1) void outproj_kernel(
    const float* __restrict__ bO, float* __restrict__ outp)
{
    const int m0 = blockIdx.x * 256;
    const int n0 = blockIdx.y * 128;

    GEMM_BODY(
        (g_Z   + (size_t)(m0 + row)*D_ + k0 + f_c*4),
        (g_WTo + (size_t)(n0 + row)*D_ + k0 + f_c*4))

#pragma unroll
    for (int nf = 0; nf < 4; ++nf) {
        int col = n0 + wn + nf*8 + 2*t;
        float bi0 = bO[col], bi1 = bO[col+1];
#pragma unroll
        for (int mf = 0; mf < 4; ++mf) {
            int m = m0 + wm + mf*16 + g;
            *(float2*)&outp[(size_t)m*D_ + col] =
                make_float2(acc[mf][nf][0] + bi0, acc[mf][nf][1] + bi1);
            *(float2*)&outp[(size_t)(m+8)*D_ + col] =
                make_float2(acc[mf][nf][2] + bi0, acc[mf][nf][3] + bi1);
        }
    }
}

// ---------------------------------------------------------------------------
// Flash attention (causal), tf32 MMA + ldmatrix + cp.async double buffering.
// Block = 128 queries x (b,h), 8 warps x 16 q-rows, 64-key tiles.
// Deferred l-reduction (per-lane partials, quad-reduced in epilogue);
// P stored without rounding (mma reads tf32 fields = truncation).
// ---------------------------------------------------------------------------
#define ATT_SMEM_BYTES 98304

__global__ __launch_bounds__(256, 2) void att_kernel()
{
    extern __shared__ char smc[];
    char* Pp  = smc + 65536;    // 8 warps x 4096
    const uint32_t Ku  = smem_u32(smc);            // 2 bufs x 16384
    const uint32_t Vtu = Ku + 32768;               // 2 bufs x 16384
    const uint32_t Pu  = Ku + 65536;

    const int tid  = threadIdx.x;
    const int warp = tid >> 5;
    const int lane = tid & 31;
    const int t    = lane & 3;
    const int g    = lane >> 2;
    const int wq   = warp * 16;
    const uint32_t sw   = (uint32_t)(lane & 7);
    const uint32_t aSel = (uint32_t)((lane >> 4) & 1);
    const uint32_t bSel = (uint32_t)((lane >> 3) & 1);

    const int qt = gridDim.x - 1 - blockIdx.x;   // big tiles first
    const int h  = blockIdx.y;
    const int b  = blockIdx.z;
    const size_t bh  = (size_t)(b*H_ + h) * S_;
    const size_t bhv = (size_t)(b*H_ + h) * E_ * S_;
    const int q0 = qt * 128;

    const int l_row = tid >> 4, l_c4 = tid & 15;
    const uint32_t fill_off = (uint32_t)((l_c4>>3)*8192);

    auto cpFill = [&](int bbuf, int kt) {
        const float* Kb = g_K + (bh + kt*64) * E_;
        const float* Vb = g_Vt + bhv + kt*64;
        const uint32_t bo = (uint32_t)(bbuf*16384) + fill_off;
#pragma unroll
        for (int p = 0; p < 4; ++p) {
            int row = l_row + p*16;
            uint32_t so = bo + SWZ((uint32_t)(row*128 + (l_c4&7)*16));
            CP16(Ku  + so, Kb + row*E_ + l_c4*4);
            CP16(Vtu + so, Vb + (size_t)row*S_ + l_c4*4);
        }
        CP_COMMIT();
    };
    cpFill(0, 0);

    // ---- stage Q (pre-scaled/rounded) into P region, pull fragments
    {
        const float* Qb = g_Q + (bh + q0) * E_;
#pragma unroll
        for (int p = 0; p < 8; ++p) {
            int idx = tid + 256*p;
            int row = idx >> 4, c4 = idx & 15;
            float4 v = *(const float4*)(Qb + row*E_ + c4*4);
            *(float4*)(Pp + (row>>4)*4096 + (c4>>3)*2048
                       + SWZ((uint32_t)((row&15)*128 + (c4&7)*16))) = v;
        }
    }
    __syncthreads();
    const uint32_t pw = Pu + warp*4096;
    unsigned qf[8][4];
#pragma unroll
    for (int d8 = 0; d8 < 8; ++d8) {
        uint32_t addr = pw + (uint32_t)((d8>>2)*2048) + (uint32_t)((lane&15)*128)
                        + ((((uint32_t)(2*(d8&3)) + aSel) ^ sw) << 4);
        LDSM4(qf[d8][0], qf[d8][1], qf[d8][2], qf[d8][3], addr);
    }

    uint32_t kB[4], vB[4];
#pragma unroll
    for (int q = 0; q < 4; ++q) {
        uint32_t r = (uint32_t)(q*16 + ((lane>>4)&1)*8 + (lane&7)) * 128u;
        kB[q] = Ku  + r;
        vB[q] = Vtu + r;
    }

    float O[8][4];
#pragma unroll
    for (int nf = 0; nf < 8; ++nf)
#pragma unroll
        for (int c = 0; c < 4; ++c) O[nf][c] = 0.f;
    float mA = -1e30f, mB = -1e30f, lA = 0.f, lB = 0.f;

    const int rowA = q0 + wq + g;
    const int rowB = rowA + 8;
    const int tmax = 2*qt + 1;
    int bb = 0;

    for (int kt = 0; kt <= tmax; ++kt) {
        CP_WAIT0();
        __syncthreads();
        if (kt < tmax) cpFill(bb ^ 1, kt + 1);
        const uint32_t bo = (uint32_t)(bb * 16384);

        // ---- S = Q K^T
        float sv[8][4];
#pragma unroll
        for (int nf = 0; nf < 8; ++nf)
#pragma unroll
            for (int c = 0; c < 4; ++c) sv[nf][c] = 0.f;
#pragma unroll
        for (int d8 = 0; d8 < 8; ++d8) {
            uint32_t ofs = bo + ((((uint32_t)(2*(d8&3)) + bSel) ^ sw) << 4)
                           + (uint32_t)((d8>>2)*8192);
#pragma unroll
            for (int q = 0; q < 4; ++q) {
                unsigned b0, b1, b2, b3;
                LDSM4(b0, b1, b2, b3, kB[q] + ofs);
                mma8(sv[2*q],   qf[d8], b0, b1);
                mma8(sv[2*q+1], qf[d8], b2, b3);
            }
        }

        // ---- causal mask (scale+log2e pre-folded into Q)
        const bool edge = (kt >= 2*qt);
        if (edge) {
#pragma unroll
            for (int nf = 0; nf < 8; ++nf) {
                int cb = kt*64 + nf*8 + 2*t;
                if (cb   > rowA) sv[nf][0] = -1e30f;
                if (cb+1 > rowA) sv[nf][1] = -1e30f;
                if (cb   > rowB) sv[nf][2] = -1e30f;
                if (cb+1 > rowB) sv[nf][3] = -1e30f;
            }
        }

        // ---- warp-local online softmax (base-2), deferred l-reduction
        float rmA = -1e30f, rmB = -1e30f;
#pragma unroll
        for (int nf = 0; nf < 8; ++nf) {
            rmA = fmaxf(rmA, fmaxf(sv[nf][0], sv[nf][1]));
            rmB = fmaxf(rmB, fmaxf(sv[nf][2], sv[nf][3]));
        }
        rmA = fmaxf(rmA, __shfl_xor_sync(0xffffffffu, rmA, 1));
        rmA = fmaxf(rmA, __shfl_xor_sync(0xffffffffu, rmA, 2));
        rmB = fmaxf(rmB, __shfl_xor_sync(0xffffffffu, rmB, 1));
        rmB = fmaxf(rmB, __shfl_xor_sync(0xffffffffu, rmB, 2));

        float mnA = fmaxf(mA, rmA), mnB = fmaxf(mB, rmB);
        float corrA = exp2f(mA - mnA), corrB = exp2f(mB - mnB);
        float rsA = 0.f, rsB = 0.f;
#pragma unroll
        for (int nf = 0; nf < 8; ++nf) {
            float p0 = exp2f(sv[nf][0] - mnA);
            float p1 = exp2f(sv[nf][1] - mnA);
            float p2 = exp2f(sv[nf][2] - mnB);
            float p3 = exp2f(sv[nf][3] - mnB);
            rsA += p0 + p1; rsB += p2 + p3;
            uint32_t poff = (uint32_t)((nf>>2)*2048);
            uint32_t in0 = (uint32_t)(((nf&3)*8 + 2*t)*4);
            *(float2*)((char*)Pp + (pw - Pu) + poff
                       + SWZ((uint32_t)(g*128) + in0)) = make_float2(p0, p1);
            *(float2*)((char*)Pp + (pw - Pu) + poff
                       + SWZ((uint32_t)((g+8)*128) + in0)) = make_float2(p2, p3);
        }
        // per-lane partials; quad-reduced once in epilogue (m is quad-uniform)
        lA = lA*corrA + rsA; mA = mnA;
        lB = lB*corrB + rsB; mB = mnB;
#pragma unroll
        for (int nf = 0; nf < 8; ++nf) {
            O[nf][0] *= corrA; O[nf][1] *= corrA;
            O[nf][2] *= corrB; O[nf][3] *= corrB;
        }
        __syncwarp();

        // ---- O += P V
#pragma unroll
        for (int kk = 0; kk < 8; ++kk) {
            uint32_t pofs = pw + (uint32_t)((kk>>2)*2048)
                            + (uint32_t)((lane&15)*128)
                            + ((((uint32_t)(2*(kk&3)) + aSel) ^ sw) << 4);
            unsigned pa[4];
            LDSM4(pa[0], pa[1], pa[2], pa[3], pofs);
            uint32_t ofs = bo + ((((uint32_t)(2*(kk&3)) + bSel) ^ sw) << 4)
                           + (uint32_t)((kk>>2)*8192);
#pragma unroll
            for (int q = 0; q < 4; ++q) {
                unsigned b0, b1, b2, b3;
                LDSM4(b0, b1, b2, b3, vB[q] + ofs);
                mma8(O[2*q],   pa, b0, b1);
                mma8(O[2*q+1], pa, b2, b3);
            }
        }
        bb ^= 1;
    }

    // ---- epilogue: quad-reduce l, normalize, write z (tf32-rounded)
    lA += __shfl_xor_sync(0xffffffffu, lA, 1);
    lA += __shfl_xor_sync(0xffffffffu, lA, 2);
    lB += __shfl_xor_sync(0xffffffffu, lB, 1);
    lB += __shfl_xor_sync(0xffffffffu, lB, 2);
    float invA = 1.0f / lA, invB = 1.0f / lB;
    float* zA = g_Z + (size_t)(b*S_ + q0 + wq + g    )*(H_*E_) + h*E_;
    float* zB = g_Z + (size_t)(b*S_ + q0 + wq + g + 8)*(H_*E_) + h*E_;
#pragma unroll
    for (int nf = 0; nf < 8; ++nf) {
        int col = nf*8 + 2*t;
        *(float2*)(zA + col) = make_float2(tf32r(O[nf][0]*invA), tf32r(O[nf][1]*invA));
        *(float2*)(zB + col) = make_float2(tf32r(O[nf][2]*invB), tf32r(O[nf][3]*invB));
    }
}

// ---------------------------------------------------------------------------
extern "C" void kernel_launch(void* const* d_in, const int* in_sizes, int n_in,
                              void* d_out, int out_size)
{
    const float* x   = (const float*)d_in[0];
    const float* W_Q = (const float*)d_in[1];
    const float* b_Q = (const float*)d_in[2];
    const float* W_K = (const float*)d_in[3];
    const float* b_K = (const float*)d_in[4];
    const float* W_V = (const float*)d_in[5];
    const float* b_V = (const float*)d_in[6];
    const float* W_O = (const float*)d_in[7];
    const float* b_O = (const float*)d_in[8];
    float* out = (float*)d_out;

    cudaFuncSetAttribute(att_kernel,
        cudaFuncAttributeMaxDynamicSharedMemorySize, ATT_SMEM_BYTES);
    cudaFuncSetAttribute(qkv_kernel,
        cudaFuncAttributeMaxDynamicSharedMemorySize, GEMM_SMEM_BYTES);
    cudaFuncSetAttribute(outproj_kernel,
        cudaFuncAttributeMaxDynamicSharedMemorySize, GEMM_SMEM_BYTES);

    round_x<<<(M_*D_/4)/256, 256>>>(x);
    dim3 tb(32, 8);
    transpose_qkv<<<dim3(32, 2, 48), tb>>>(W_Q, W_K, W_V);
    transpose_wo<<<dim3(32, 32, 1), tb>>>(W_O);

    dim3 gqkv(M_/256, 24);
    qkv_kernel<<<gqkv, 512, GEMM_SMEM_BYTES>>>(b_Q, b_K, b_V);

    dim3 gatt(S_/128, H_, B_);
    att_kernel<<<gatt, 256, ATT_SMEM_BYTES>>>();

    dim3 gout(M_/256, D_/128);
    outproj_kernel<<<gout, 512, GEMM_SMEM_BYTES>>>(b_O, out);
}